// round 6
// baseline (speedup 1.0000x reference)
#include <cuda_runtime.h>
#include <cuda_bf16.h>
#include <cstdint>

#define N_NODES 50000
#define N_EDGES 800000
#define F 128

// ---------------- scratch (static device memory) -----------------------------
__device__ unsigned g_xp[(size_t)N_NODES * F];          // packed split-bf16 x (hi lo)
__device__ unsigned g_hp[2][(size_t)N_NODES * F];       // packed hidden (ping-pong)
__device__ unsigned g_meanp[(size_t)N_NODES * F];       // packed mean
__device__ __nv_bfloat16 g_whi[3 * 128 * 256];          // combined [Wl|Wr] hi
__device__ __nv_bfloat16 g_wlo[3 * 128 * 256];          // combined [Wl|Wr] lo
__device__ int g_deg[N_NODES];
__device__ int g_off[N_NODES];
__device__ int g_cursor[N_NODES];
__device__ int g_srcs[N_EDGES];

// ---------------- pack/unpack helpers ----------------------------------------
__device__ __forceinline__ float unpack_v(unsigned u) {
    return __uint_as_float(u << 16) + __uint_as_float(u & 0xFFFF0000u);
}
__device__ __forceinline__ unsigned pack_v(float v) {
    __nv_bfloat16 h = __float2bfloat16(v);
    unsigned hb = (unsigned)__bfloat16_as_ushort(h);
    float hf = __uint_as_float(hb << 16);
    __nv_bfloat16 l = __float2bfloat16(v - hf);
    unsigned lb = (unsigned)__bfloat16_as_ushort(l);
    return hb | (lb << 16);
}

// ---------------- warp-mma helpers --------------------------------------------
__device__ __forceinline__ unsigned smem_u32(const void* p) {
    unsigned a;
    asm("{ .reg .u64 t; cvta.to.shared.u64 t, %1; cvt.u32.u64 %0, t; }" : "=r"(a) : "l"(p));
    return a;
}
__device__ __forceinline__ void ldsm_x4(unsigned* r, unsigned addr) {
    asm volatile("ldmatrix.sync.aligned.m8n8.x4.shared.b16 {%0,%1,%2,%3}, [%4];"
                 : "=r"(r[0]), "=r"(r[1]), "=r"(r[2]), "=r"(r[3]) : "r"(addr));
}
__device__ __forceinline__ void mma16816(float* c, const unsigned* a, const unsigned* b) {
    asm volatile(
        "mma.sync.aligned.m16n8k16.row.col.f32.bf16.bf16.f32 "
        "{%0,%1,%2,%3}, {%4,%5,%6,%7}, {%8,%9}, {%0,%1,%2,%3};"
        : "+f"(c[0]), "+f"(c[1]), "+f"(c[2]), "+f"(c[3])
        : "r"(a[0]), "r"(a[1]), "r"(a[2]), "r"(a[3]), "r"(b[0]), "r"(b[1]));
}

// ---------------- CSR build ------------------------------------------------------
__global__ void k_hist(const int* __restrict__ edge) {
    int e = blockIdx.x * blockDim.x + threadIdx.x;
    if (e < N_EDGES) {
        unsigned dst = (unsigned)edge[N_EDGES + e];
        if (dst < N_NODES) atomicAdd(&g_deg[dst], 1);
    }
}

// single-block scan: 1024 threads, each owns 49 consecutive nodes
#define NODES_PER_T 49
__global__ void __launch_bounds__(1024, 1) k_scan_all() {
    __shared__ int part[1024];
    int t = threadIdx.x;
    int base = t * NODES_PER_T;
    int sum = 0;
#pragma unroll 7
    for (int i = 0; i < NODES_PER_T; i++) {
        int n = base + i;
        if (n < N_NODES) sum += g_deg[n];
    }
    part[t] = sum;
    __syncthreads();
    // block inclusive scan
    for (int o = 1; o < 1024; o <<= 1) {
        int v = (t >= o) ? part[t - o] : 0;
        __syncthreads();
        part[t] += v;
        __syncthreads();
    }
    int run = part[t] - sum;   // exclusive prefix for this thread's range
#pragma unroll 7
    for (int i = 0; i < NODES_PER_T; i++) {
        int n = base + i;
        if (n < N_NODES) {
            g_off[n] = run;
            g_cursor[n] = run;
            run += g_deg[n];
        }
    }
}

__global__ void k_scatter(const int* __restrict__ edge) {
    int e = blockIdx.x * blockDim.x + threadIdx.x;
    if (e < N_EDGES) {
        unsigned src = (unsigned)edge[e];
        unsigned dst = (unsigned)edge[N_EDGES + e];
        if (dst < N_NODES && src < N_NODES) {
            int pos = atomicAdd(&g_cursor[dst], 1);
            g_srcs[pos] = (int)src;
        }
    }
}

// ---------------- fused prep: zero deg + pack x + pack weights ------------------
__global__ void k_prep(const float* __restrict__ x,
                       const float* Wl0, const float* Wr0,
                       const float* Wl1, const float* Wr1,
                       const float* Wl2, const float* Wr2) {
    int gid = blockIdx.x * blockDim.x + threadIdx.x;
    if (gid < N_NODES) g_deg[gid] = 0;
    if (gid < 3 * 128 * 256) {
        int L = gid / (128 * 256);
        int r = gid % (128 * 256);
        int n = r / 256;
        int k = r % 256;
        const float* Wl = (L == 0) ? Wl0 : (L == 1) ? Wl1 : Wl2;
        const float* Wr = (L == 0) ? Wr0 : (L == 1) ? Wr1 : Wr2;
        float v = (k < 128) ? Wl[n * 128 + k] : Wr[n * 128 + (k - 128)];
        unsigned p = pack_v(v);
        __nv_bfloat16_raw hr; hr.x = (unsigned short)(p & 0xFFFF);
        __nv_bfloat16_raw lr; lr.x = (unsigned short)(p >> 16);
        g_whi[gid] = __nv_bfloat16(hr);
        g_wlo[gid] = __nv_bfloat16(lr);
    }
    // pack x: one thread per 4 features
    if (gid < N_NODES * F / 4) {
        float4 v = ((const float4*)x)[gid];
        uint4 o;
        o.x = pack_v(v.x); o.y = pack_v(v.y); o.z = pack_v(v.z); o.w = pack_v(v.w);
        ((uint4*)g_xp)[gid] = o;
    }
}

// ---------------- aggregation: warp per node, 4x unrolled gathers ---------------
__global__ void k_agg(const unsigned* __restrict__ in) {
    int node = (blockIdx.x * blockDim.x + threadIdx.x) >> 5;
    if (node >= N_NODES) return;
    int lane = threadIdx.x & 31;
    int d = g_deg[node];
    int o = g_off[node];
    float a0 = 0.f, a1 = 0.f, a2 = 0.f, a3 = 0.f;
    int e = 0;
    for (; e + 4 <= d; e += 4) {
        int s0 = g_srcs[o + e];
        int s1 = g_srcs[o + e + 1];
        int s2 = g_srcs[o + e + 2];
        int s3 = g_srcs[o + e + 3];
        uint4 p0 = ((const uint4*)(in + (size_t)s0 * F))[lane];
        uint4 p1 = ((const uint4*)(in + (size_t)s1 * F))[lane];
        uint4 p2 = ((const uint4*)(in + (size_t)s2 * F))[lane];
        uint4 p3 = ((const uint4*)(in + (size_t)s3 * F))[lane];
        a0 += unpack_v(p0.x) + unpack_v(p1.x) + unpack_v(p2.x) + unpack_v(p3.x);
        a1 += unpack_v(p0.y) + unpack_v(p1.y) + unpack_v(p2.y) + unpack_v(p3.y);
        a2 += unpack_v(p0.z) + unpack_v(p1.z) + unpack_v(p2.z) + unpack_v(p3.z);
        a3 += unpack_v(p0.w) + unpack_v(p1.w) + unpack_v(p2.w) + unpack_v(p3.w);
    }
    for (; e < d; e++) {
        int s = g_srcs[o + e];
        uint4 p = ((const uint4*)(in + (size_t)s * F))[lane];
        a0 += unpack_v(p.x); a1 += unpack_v(p.y);
        a2 += unpack_v(p.z); a3 += unpack_v(p.w);
    }
    float inv = (d > 0) ? 1.0f / (float)d : 0.0f;
    uint4 outp;
    outp.x = pack_v(a0 * inv); outp.y = pack_v(a1 * inv);
    outp.z = pack_v(a2 * inv); outp.w = pack_v(a3 * inv);
    ((uint4*)(g_meanp + (size_t)node * F))[lane] = outp;
}

// ---------------- HMMA GEMM: relu([mean|h] @ [Wl|Wr]^T + b), split bf16 ---------
#define SM_BIAS 0
#define SM_AHI  512
#define SM_ALO  (SM_AHI + 16384)
#define SM_WHI  (SM_ALO + 16384)
#define SM_WLO  (SM_WHI + 16384)
#define SM_TOTAL (SM_WLO + 16384)     // 66048 bytes

__device__ __forceinline__ unsigned swoff(int row, int k) {
    return (unsigned)(row * 128 + ((((k >> 3) ^ row) & 7) << 4) + (k & 7) * 2);
}

__global__ void __launch_bounds__(256, 1) k_gemm(
    const unsigned* __restrict__ Am,
    const unsigned* __restrict__ Ah,
    const __nv_bfloat16* __restrict__ Whi,
    const __nv_bfloat16* __restrict__ Wlo,
    const float* __restrict__ bl,
    unsigned* __restrict__ outp)
{
    extern __shared__ __align__(16) char smem[];
    unsigned sb = smem_u32(smem);
    int tid = threadIdx.x;
    int wid = tid >> 5;
    int lane = tid & 31;
    int wm = wid & 1;
    int wn = wid >> 1;
    int m0 = blockIdx.x * 128;

    if (tid < 128) *(float*)(smem + SM_BIAS + tid * 4) = bl[tid];

    float acc[4][4][4];
#pragma unroll
    for (int a = 0; a < 4; a++)
#pragma unroll
        for (int b = 0; b < 4; b++)
#pragma unroll
            for (int c = 0; c < 4; c++) acc[a][b][c] = 0.f;

    for (int chunk = 0; chunk < 4; chunk++) {
        const unsigned* ap = (chunk < 2) ? Am : Ah;
        int kcA = (chunk & 1) * 64;
        int kcW = chunk * 64;
        __syncthreads();
        for (int i = tid; i < 2048; i += 256) {
            int row = i >> 4;
            int k4 = (i & 15) * 4;
            uint4 p = make_uint4(0, 0, 0, 0);
            if (m0 + row < N_NODES)
                p = *(const uint4*)(ap + (size_t)(m0 + row) * F + kcA + k4);
            uint2 h, l;
            h.x = (p.x & 0xFFFFu) | (p.y << 16);
            h.y = (p.z & 0xFFFFu) | (p.w << 16);
            l.x = (p.x >> 16) | (p.y & 0xFFFF0000u);
            l.y = (p.z >> 16) | (p.w & 0xFFFF0000u);
            unsigned off = swoff(row, k4);
            *(uint2*)(smem + SM_AHI + off) = h;
            *(uint2*)(smem + SM_ALO + off) = l;
        }
        for (int i = tid; i < 1024; i += 256) {
            int n = i >> 3;
            int k8 = (i & 7) * 8;
            unsigned off = swoff(n, k8);
            *(uint4*)(smem + SM_WHI + off) = *(const uint4*)(Whi + n * 256 + kcW + k8);
            *(uint4*)(smem + SM_WLO + off) = *(const uint4*)(Wlo + n * 256 + kcW + k8);
        }
        __syncthreads();

#pragma unroll
        for (int ks = 0; ks < 4; ks++) {
            int kl = ks * 16;
            unsigned ahi[16], alo[16];
            int mrl = ((lane >> 3) & 1) * 8 + (lane & 7);
            int kkA = kl + (lane >> 4) * 8;
#pragma unroll
            for (int mf = 0; mf < 4; mf++) {
                int mrow = wm * 64 + mf * 16 + mrl;
                unsigned offA = (unsigned)(mrow * 128 + ((((kkA >> 3) ^ mrow) & 7) << 4));
                ldsm_x4(&ahi[mf * 4], sb + SM_AHI + offA);
                ldsm_x4(&alo[mf * 4], sb + SM_ALO + offA);
            }
            unsigned bhi[8], blo[8];
            int nrl = (lane >> 4) * 8 + (lane & 7);
            int kkB = kl + ((lane >> 3) & 1) * 8;
#pragma unroll
            for (int nf2 = 0; nf2 < 2; nf2++) {
                int nrow = wn * 32 + nf2 * 16 + nrl;
                unsigned offB = (unsigned)(nrow * 128 + ((((kkB >> 3) ^ nrow) & 7) << 4));
                ldsm_x4(&bhi[nf2 * 4], sb + SM_WHI + offB);
                ldsm_x4(&blo[nf2 * 4], sb + SM_WLO + offB);
            }
#pragma unroll
            for (int mf = 0; mf < 4; mf++)
#pragma unroll
                for (int nf = 0; nf < 4; nf++) {
                    const unsigned* bh = &bhi[(nf >> 1) * 4 + (nf & 1) * 2];
                    const unsigned* blp = &blo[(nf >> 1) * 4 + (nf & 1) * 2];
                    mma16816(acc[mf][nf], &ahi[mf * 4], bh);
                    mma16816(acc[mf][nf], &ahi[mf * 4], blp);
                    mma16816(acc[mf][nf], &alo[mf * 4], bh);
                }
        }
    }

    // epilogue: bias + relu + pack
    const float* bias = (const float*)(smem + SM_BIAS);
#pragma unroll
    for (int mf = 0; mf < 4; mf++) {
        int ra = m0 + wm * 64 + mf * 16 + (lane >> 2);
        int rb = ra + 8;
#pragma unroll
        for (int nf = 0; nf < 4; nf++) {
            int col = wn * 32 + nf * 8 + (lane & 3) * 2;
            float b0 = bias[col], b1 = bias[col + 1];
            if (ra < N_NODES) {
                float v0 = fmaxf(acc[mf][nf][0] + b0, 0.f);
                float v1 = fmaxf(acc[mf][nf][1] + b1, 0.f);
                *(uint2*)(outp + (size_t)ra * F + col) = make_uint2(pack_v(v0), pack_v(v1));
            }
            if (rb < N_NODES) {
                float v2 = fmaxf(acc[mf][nf][2] + b0, 0.f);
                float v3 = fmaxf(acc[mf][nf][3] + b1, 0.f);
                *(uint2*)(outp + (size_t)rb * F + col) = make_uint2(pack_v(v2), pack_v(v3));
            }
        }
    }
}

// ---------------- final linear ----------------------------------------------------
__global__ void k_final(const unsigned* __restrict__ h,
                        const float* __restrict__ Wf,
                        const float* __restrict__ bf,
                        float* __restrict__ out)
{
    int node = (blockIdx.x * blockDim.x + threadIdx.x) >> 5;
    if (node >= N_NODES) return;
    int lane = threadIdx.x & 31;
    uint4 p = ((const uint4*)(h + (size_t)node * F))[lane];
    float4 wv = ((const float4*)Wf)[lane];
    float s = unpack_v(p.x) * wv.x + unpack_v(p.y) * wv.y +
              unpack_v(p.z) * wv.z + unpack_v(p.w) * wv.w;
#pragma unroll
    for (int o = 16; o > 0; o >>= 1) s += __shfl_down_sync(0xFFFFFFFFu, s, o);
    if (lane == 0) out[node] = s + bf[0];
}

// ---------------- launch ------------------------------------------------------------
extern "C" void kernel_launch(void* const* d_in, const int* in_sizes, int n_in,
                              void* d_out, int out_size)
{
    const float* x    = (const float*)d_in[0];
    const int*   edge = (const int*)d_in[1];   // int32 (JAX x64 disabled)
    const float* Wl[3] = {(const float*)d_in[2], (const float*)d_in[5], (const float*)d_in[8]};
    const float* bl[3] = {(const float*)d_in[3], (const float*)d_in[6], (const float*)d_in[9]};
    const float* Wr[3] = {(const float*)d_in[4], (const float*)d_in[7], (const float*)d_in[10]};
    const float* Wf = (const float*)d_in[11];
    const float* bf = (const float*)d_in[12];
    float* out = (float*)d_out;

    cudaFuncSetAttribute(k_gemm, cudaFuncAttributeMaxDynamicSharedMemorySize, SM_TOTAL);

    void* p = nullptr;
    cudaGetSymbolAddress(&p, g_xp);
    unsigned* xp = (unsigned*)p;
    cudaGetSymbolAddress(&p, g_hp);
    unsigned* h0 = (unsigned*)p;
    unsigned* h1 = h0 + (size_t)N_NODES * F;
    cudaGetSymbolAddress(&p, g_meanp);
    unsigned* mp = (unsigned*)p;
    cudaGetSymbolAddress(&p, g_whi);
    __nv_bfloat16* whi = (__nv_bfloat16*)p;
    cudaGetSymbolAddress(&p, g_wlo);
    __nv_bfloat16* wlo = (__nv_bfloat16*)p;

    // prep (zero deg + pack x + pack W), then CSR build
    k_prep<<<(N_NODES * F / 4 + 255) / 256, 256>>>(x, Wl[0], Wr[0], Wl[1], Wr[1], Wl[2], Wr[2]);
    k_hist<<<(N_EDGES + 255) / 256, 256>>>(edge);
    k_scan_all<<<1, 1024>>>();
    k_scatter<<<(N_EDGES + 255) / 256, 256>>>(edge);

    const int AGG_BLOCKS = (N_NODES * 32 + 255) / 256;
    const int GEMM_BLOCKS = (N_NODES + 127) / 128;   // 391

    // layer 0
    k_agg<<<AGG_BLOCKS, 256>>>(xp);
    k_gemm<<<GEMM_BLOCKS, 256, SM_TOTAL>>>(mp, xp, whi, wlo, bl[0], h0);
    // layer 1
    k_agg<<<AGG_BLOCKS, 256>>>(h0);
    k_gemm<<<GEMM_BLOCKS, 256, SM_TOTAL>>>(mp, h0, whi + 128 * 256, wlo + 128 * 256, bl[1], h1);
    // layer 2
    k_agg<<<AGG_BLOCKS, 256>>>(h1);
    k_gemm<<<GEMM_BLOCKS, 256, SM_TOTAL>>>(mp, h1, whi + 2 * 128 * 256, wlo + 2 * 128 * 256, bl[2], h0);
    // final
    k_final<<<AGG_BLOCKS, 256>>>(h0, Wf, bf, out);
}

// round 7
// speedup vs baseline: 1.1208x; 1.1208x over previous
#include <cuda_runtime.h>
#include <cuda_bf16.h>
#include <cstdint>

#define N_NODES 50000
#define N_EDGES 800000
#define F 128
#define SCAN_BLK 1024
#define NSCAN ((N_NODES + SCAN_BLK - 1) / SCAN_BLK)   // 49

// ---------------- scratch (static device memory) -----------------------------
__device__ unsigned g_xp[(size_t)N_NODES * F];          // packed split-bf16 x
__device__ unsigned g_hp[2][(size_t)N_NODES * F];       // packed hidden
__device__ unsigned g_meanp[(size_t)N_NODES * F];       // packed mean
__device__ short    g_xq[(size_t)N_NODES * F];          // int16 x (gather fmt)
__device__ short    g_hq[2][(size_t)N_NODES * F];       // int16 hidden
__device__ float    g_sx[N_NODES];                      // row scales
__device__ float    g_sh[2][N_NODES];
__device__ __nv_bfloat16 g_whi[3 * 128 * 256];
__device__ __nv_bfloat16 g_wlo[3 * 128 * 256];
__device__ int g_deg[N_NODES];
__device__ int g_scan[N_NODES];
__device__ int g_off[N_NODES];
__device__ int g_cursor[N_NODES];
__device__ int g_bsum[64];
__device__ int g_bsumx[64];
__device__ int g_srcs[N_EDGES];

// ---------------- helpers ------------------------------------------------------
__device__ __forceinline__ unsigned pack_v(float v) {
    __nv_bfloat16 h = __float2bfloat16(v);
    unsigned hb = (unsigned)__bfloat16_as_ushort(h);
    float hf = __uint_as_float(hb << 16);
    __nv_bfloat16 l = __float2bfloat16(v - hf);
    return hb | ((unsigned)__bfloat16_as_ushort(l) << 16);
}
__device__ __forceinline__ float unpack_v(unsigned u) {
    return __uint_as_float(u << 16) + __uint_as_float(u & 0xFFFF0000u);
}
__device__ __forceinline__ unsigned smem_u32(const void* p) {
    unsigned a;
    asm("{ .reg .u64 t; cvta.to.shared.u64 t, %1; cvt.u32.u64 %0, t; }" : "=r"(a) : "l"(p));
    return a;
}
__device__ __forceinline__ void ldsm_x4(unsigned* r, unsigned addr) {
    asm volatile("ldmatrix.sync.aligned.m8n8.x4.shared.b16 {%0,%1,%2,%3}, [%4];"
                 : "=r"(r[0]), "=r"(r[1]), "=r"(r[2]), "=r"(r[3]) : "r"(addr));
}
__device__ __forceinline__ void mma16816(float* c, const unsigned* a, const unsigned* b) {
    asm volatile(
        "mma.sync.aligned.m16n8k16.row.col.f32.bf16.bf16.f32 "
        "{%0,%1,%2,%3}, {%4,%5,%6,%7}, {%8,%9}, {%0,%1,%2,%3};"
        : "+f"(c[0]), "+f"(c[1]), "+f"(c[2]), "+f"(c[3])
        : "r"(a[0]), "r"(a[1]), "r"(a[2]), "r"(a[3]), "r"(b[0]), "r"(b[1]));
}

// ---------------- CSR build -----------------------------------------------------
__global__ void k_hist(const int* __restrict__ edge) {
    int e = blockIdx.x * blockDim.x + threadIdx.x;
    if (e < N_EDGES) {
        unsigned dst = (unsigned)edge[N_EDGES + e];
        if (dst < N_NODES) atomicAdd(&g_deg[dst], 1);
    }
}
__global__ void k_scan1() {
    __shared__ int s[SCAN_BLK];
    int tid = threadIdx.x;
    int i = blockIdx.x * SCAN_BLK + tid;
    int v = (i < N_NODES) ? g_deg[i] : 0;
    s[tid] = v;
    __syncthreads();
    for (int o = 1; o < SCAN_BLK; o <<= 1) {
        int t = (tid >= o) ? s[tid - o] : 0;
        __syncthreads();
        s[tid] += t;
        __syncthreads();
    }
    if (i < N_NODES) g_scan[i] = s[tid];
    if (tid == SCAN_BLK - 1) g_bsum[blockIdx.x] = s[tid];
}
__global__ void k_scan2() {
    __shared__ int s[64];
    int tid = threadIdx.x;
    int v = (tid < NSCAN) ? g_bsum[tid] : 0;
    s[tid] = v;
    __syncthreads();
    for (int o = 1; o < 64; o <<= 1) {
        int t = (tid >= o) ? s[tid - o] : 0;
        __syncthreads();
        s[tid] += t;
        __syncthreads();
    }
    if (tid < NSCAN) g_bsumx[tid] = s[tid] - v;
}
__global__ void k_scan3() {
    int i = blockIdx.x * blockDim.x + threadIdx.x;
    if (i < N_NODES) {
        int off = g_scan[i] - g_deg[i] + g_bsumx[i / SCAN_BLK];
        g_off[i] = off;
        g_cursor[i] = off;
    }
}
__global__ void k_scatter(const int* __restrict__ edge) {
    int e = blockIdx.x * blockDim.x + threadIdx.x;
    if (e < N_EDGES) {
        unsigned src = (unsigned)edge[e];
        unsigned dst = (unsigned)edge[N_EDGES + e];
        if (dst < N_NODES && src < N_NODES) {
            int pos = atomicAdd(&g_cursor[dst], 1);
            g_srcs[pos] = (int)src;
        }
    }
}

// ---------------- prep: zero deg + pack W + dual-format x ----------------------
__global__ void k_prep(const float* __restrict__ x,
                       const float* Wl0, const float* Wr0,
                       const float* Wl1, const float* Wr1,
                       const float* Wl2, const float* Wr2) {
    int gid = blockIdx.x * blockDim.x + threadIdx.x;
    if (gid < N_NODES) g_deg[gid] = 0;
    if (gid < 3 * 128 * 256) {
        int L = gid / (128 * 256);
        int r = gid % (128 * 256);
        int n = r / 256;
        int k = r % 256;
        const float* Wl = (L == 0) ? Wl0 : (L == 1) ? Wl1 : Wl2;
        const float* Wr = (L == 0) ? Wr0 : (L == 1) ? Wr1 : Wr2;
        float v = (k < 128) ? Wl[n * 128 + k] : Wr[n * 128 + (k - 128)];
        unsigned p = pack_v(v);
        __nv_bfloat16_raw hr; hr.x = (unsigned short)(p & 0xFFFF);
        __nv_bfloat16_raw lr; lr.x = (unsigned short)(p >> 16);
        g_whi[gid] = __nv_bfloat16(hr);
        g_wlo[gid] = __nv_bfloat16(lr);
    }
    // dual-format x: warp per row (32 threads x 4 feats)
    int row = gid >> 5;
    int lane = gid & 31;
    if (row < N_NODES) {
        float4 v = ((const float4*)x)[gid];
        uint4 o;
        o.x = pack_v(v.x); o.y = pack_v(v.y); o.z = pack_v(v.z); o.w = pack_v(v.w);
        ((uint4*)g_xp)[gid] = o;
        float m = fmaxf(fmaxf(fabsf(v.x), fabsf(v.y)), fmaxf(fabsf(v.z), fabsf(v.w)));
#pragma unroll
        for (int of = 16; of > 0; of >>= 1) m = fmaxf(m, __shfl_xor_sync(0xFFFFFFFFu, m, of));
        float qs = (m > 0.f) ? 32766.f / m : 0.f;
        int q0 = __float2int_rn(v.x * qs), q1 = __float2int_rn(v.y * qs);
        int q2 = __float2int_rn(v.z * qs), q3 = __float2int_rn(v.w * qs);
        uint2 oq;
        oq.x = (q0 & 0xFFFF) | (q1 << 16);
        oq.y = (q2 & 0xFFFF) | (q3 << 16);
        ((uint2*)g_xq)[gid] = oq;
        if (lane == 0) g_sx[row] = m / 32766.f;
    }
}

// ---------------- aggregation: warp per node, int16 gather, packed output ------
__global__ void k_agg(const short* __restrict__ inq, const float* __restrict__ ins) {
    int node = (blockIdx.x * blockDim.x + threadIdx.x) >> 5;
    if (node >= N_NODES) return;
    int lane = threadIdx.x & 31;
    int d = g_deg[node];
    int o = g_off[node];
    float a0 = 0.f, a1 = 0.f, a2 = 0.f, a3 = 0.f;
    int e = 0;
    for (; e + 2 <= d; e += 2) {
        int s0 = g_srcs[o + e];
        int s1 = g_srcs[o + e + 1];
        float c0 = ins[s0], c1 = ins[s1];
        uint2 p0 = ((const uint2*)(inq + (size_t)s0 * F))[lane];
        uint2 p1 = ((const uint2*)(inq + (size_t)s1 * F))[lane];
        short2 u0 = *(short2*)&p0.x, u1 = *(short2*)&p0.y;
        short2 v0 = *(short2*)&p1.x, v1 = *(short2*)&p1.y;
        a0 += (float)u0.x * c0 + (float)v0.x * c1;
        a1 += (float)u0.y * c0 + (float)v0.y * c1;
        a2 += (float)u1.x * c0 + (float)v1.x * c1;
        a3 += (float)u1.y * c0 + (float)v1.y * c1;
    }
    if (e < d) {
        int s = g_srcs[o + e];
        float c = ins[s];
        uint2 p = ((const uint2*)(inq + (size_t)s * F))[lane];
        short2 u0 = *(short2*)&p.x, u1 = *(short2*)&p.y;
        a0 += (float)u0.x * c; a1 += (float)u0.y * c;
        a2 += (float)u1.x * c; a3 += (float)u1.y * c;
    }
    float inv = (d > 0) ? 1.0f / (float)d : 0.0f;
    uint4 outp;
    outp.x = pack_v(a0 * inv); outp.y = pack_v(a1 * inv);
    outp.z = pack_v(a2 * inv); outp.w = pack_v(a3 * inv);
    ((uint4*)(g_meanp + (size_t)node * F))[lane] = outp;
}

// ---------------- HMMA GEMM (R4 core) + dual-format epilogue --------------------
#define SM_BIAS 0
#define SM_RMAX 512
#define SM_AHI  1024
#define SM_ALO  (SM_AHI + 16384)
#define SM_WHI  (SM_ALO + 16384)
#define SM_WLO  (SM_WHI + 16384)
#define SM_TOTAL (SM_WLO + 16384)     // 66560 bytes

__device__ __forceinline__ unsigned swoff(int row, int k) {
    return (unsigned)(row * 128 + ((((k >> 3) ^ row) & 7) << 4) + (k & 7) * 2);
}

__global__ void __launch_bounds__(256, 1) k_gemm(
    const unsigned* __restrict__ Am,
    const unsigned* __restrict__ Ah,
    const __nv_bfloat16* __restrict__ Whi,
    const __nv_bfloat16* __restrict__ Wlo,
    const float* __restrict__ bl,
    unsigned* __restrict__ outp,
    short* __restrict__ outq, float* __restrict__ outs)
{
    extern __shared__ __align__(16) char smem[];
    unsigned sb = smem_u32(smem);
    int tid = threadIdx.x;
    int wid = tid >> 5;
    int lane = tid & 31;
    int wm = wid & 1;
    int wn = wid >> 1;
    int m0 = blockIdx.x * 128;

    if (tid < 128) {
        *(float*)(smem + SM_BIAS + tid * 4) = bl[tid];
        *(int*)(smem + SM_RMAX + tid * 4) = 0;
    }

    float acc[4][4][4];
#pragma unroll
    for (int a = 0; a < 4; a++)
#pragma unroll
        for (int b = 0; b < 4; b++)
#pragma unroll
            for (int c = 0; c < 4; c++) acc[a][b][c] = 0.f;

    for (int chunk = 0; chunk < 4; chunk++) {
        const unsigned* ap = (chunk < 2) ? Am : Ah;
        int kcA = (chunk & 1) * 64;
        int kcW = chunk * 64;
        __syncthreads();
        for (int i = tid; i < 2048; i += 256) {
            int row = i >> 4;
            int k4 = (i & 15) * 4;
            uint4 p = make_uint4(0, 0, 0, 0);
            if (m0 + row < N_NODES)
                p = *(const uint4*)(ap + (size_t)(m0 + row) * F + kcA + k4);
            uint2 h, l;
            h.x = (p.x & 0xFFFFu) | (p.y << 16);
            h.y = (p.z & 0xFFFFu) | (p.w << 16);
            l.x = (p.x >> 16) | (p.y & 0xFFFF0000u);
            l.y = (p.z >> 16) | (p.w & 0xFFFF0000u);
            unsigned off = swoff(row, k4);
            *(uint2*)(smem + SM_AHI + off) = h;
            *(uint2*)(smem + SM_ALO + off) = l;
        }
        for (int i = tid; i < 1024; i += 256) {
            int n = i >> 3;
            int k8 = (i & 7) * 8;
            unsigned off = swoff(n, k8);
            *(uint4*)(smem + SM_WHI + off) = *(const uint4*)(Whi + n * 256 + kcW + k8);
            *(uint4*)(smem + SM_WLO + off) = *(const uint4*)(Wlo + n * 256 + kcW + k8);
        }
        __syncthreads();

#pragma unroll
        for (int ks = 0; ks < 4; ks++) {
            int kl = ks * 16;
            unsigned ahi[16], alo[16];
            int mrl = ((lane >> 3) & 1) * 8 + (lane & 7);
            int kkA = kl + (lane >> 4) * 8;
#pragma unroll
            for (int mf = 0; mf < 4; mf++) {
                int mrow = wm * 64 + mf * 16 + mrl;
                unsigned offA = (unsigned)(mrow * 128 + ((((kkA >> 3) ^ mrow) & 7) << 4));
                ldsm_x4(&ahi[mf * 4], sb + SM_AHI + offA);
                ldsm_x4(&alo[mf * 4], sb + SM_ALO + offA);
            }
            unsigned bhi[8], blo[8];
            int nrl = (lane >> 4) * 8 + (lane & 7);
            int kkB = kl + ((lane >> 3) & 1) * 8;
#pragma unroll
            for (int nf2 = 0; nf2 < 2; nf2++) {
                int nrow = wn * 32 + nf2 * 16 + nrl;
                unsigned offB = (unsigned)(nrow * 128 + ((((kkB >> 3) ^ nrow) & 7) << 4));
                ldsm_x4(&bhi[nf2 * 4], sb + SM_WHI + offB);
                ldsm_x4(&blo[nf2 * 4], sb + SM_WLO + offB);
            }
#pragma unroll
            for (int mf = 0; mf < 4; mf++)
#pragma unroll
                for (int nf = 0; nf < 4; nf++) {
                    const unsigned* bh = &bhi[(nf >> 1) * 4 + (nf & 1) * 2];
                    const unsigned* blp = &blo[(nf >> 1) * 4 + (nf & 1) * 2];
                    mma16816(acc[mf][nf], &ahi[mf * 4], bh);
                    mma16816(acc[mf][nf], &ahi[mf * 4], blp);
                    mma16816(acc[mf][nf], &alo[mf * 4], bh);
                }
        }
    }

    // epilogue pass 1: row maxima (post-relu, >=0 -> int-bit atomicMax valid)
    const float* bias = (const float*)(smem + SM_BIAS);
    int* rmax = (int*)(smem + SM_RMAX);
#pragma unroll
    for (int mf = 0; mf < 4; mf++) {
        int la = wm * 64 + mf * 16 + (lane >> 2);
        float mxa = 0.f, mxb = 0.f;
#pragma unroll
        for (int nf = 0; nf < 4; nf++) {
            int col = wn * 32 + nf * 8 + (lane & 3) * 2;
            float b0 = bias[col], b1 = bias[col + 1];
            mxa = fmaxf(mxa, fmaxf(acc[mf][nf][0] + b0, acc[mf][nf][1] + b1));
            mxb = fmaxf(mxb, fmaxf(acc[mf][nf][2] + b0, acc[mf][nf][3] + b1));
        }
        atomicMax(&rmax[la], __float_as_int(fmaxf(mxa, 0.f)));
        atomicMax(&rmax[la + 8], __float_as_int(fmaxf(mxb, 0.f)));
    }
    __syncthreads();
    // epilogue pass 2: packed + int16 stores
#pragma unroll
    for (int mf = 0; mf < 4; mf++) {
        int la = wm * 64 + mf * 16 + (lane >> 2);
        int ra = m0 + la;
        int rb = ra + 8;
        float ma = __int_as_float(rmax[la]);
        float mb = __int_as_float(rmax[la + 8]);
        float qa = (ma > 0.f) ? 32766.f / ma : 0.f;
        float qb = (mb > 0.f) ? 32766.f / mb : 0.f;
        if (wn == 0 && (lane & 3) == 0) {
            if (ra < N_NODES) outs[ra] = ma / 32766.f;
            if (rb < N_NODES) outs[rb] = mb / 32766.f;
        }
#pragma unroll
        for (int nf = 0; nf < 4; nf++) {
            int col = wn * 32 + nf * 8 + (lane & 3) * 2;
            float b0 = bias[col], b1 = bias[col + 1];
            if (ra < N_NODES) {
                float v0 = fmaxf(acc[mf][nf][0] + b0, 0.f);
                float v1 = fmaxf(acc[mf][nf][1] + b1, 0.f);
                *(uint2*)(outp + (size_t)ra * F + col) = make_uint2(pack_v(v0), pack_v(v1));
                int q0 = __float2int_rn(v0 * qa), q1 = __float2int_rn(v1 * qa);
                *(unsigned*)(outq + (size_t)ra * F + col) = (q0 & 0xFFFF) | (q1 << 16);
            }
            if (rb < N_NODES) {
                float v2 = fmaxf(acc[mf][nf][2] + b0, 0.f);
                float v3 = fmaxf(acc[mf][nf][3] + b1, 0.f);
                *(uint2*)(outp + (size_t)rb * F + col) = make_uint2(pack_v(v2), pack_v(v3));
                int q2 = __float2int_rn(v2 * qb), q3 = __float2int_rn(v3 * qb);
                *(unsigned*)(outq + (size_t)rb * F + col) = (q2 & 0xFFFF) | (q3 << 16);
            }
        }
    }
}

// ---------------- final linear ---------------------------------------------------
__global__ void k_final(const unsigned* __restrict__ h,
                        const float* __restrict__ Wf,
                        const float* __restrict__ bf,
                        float* __restrict__ out)
{
    int node = (blockIdx.x * blockDim.x + threadIdx.x) >> 5;
    if (node >= N_NODES) return;
    int lane = threadIdx.x & 31;
    uint4 p = ((const uint4*)(h + (size_t)node * F))[lane];
    float4 wv = ((const float4*)Wf)[lane];
    float s = unpack_v(p.x) * wv.x + unpack_v(p.y) * wv.y +
              unpack_v(p.z) * wv.z + unpack_v(p.w) * wv.w;
#pragma unroll
    for (int o = 16; o > 0; o >>= 1) s += __shfl_down_sync(0xFFFFFFFFu, s, o);
    if (lane == 0) out[node] = s + bf[0];
}

// ---------------- launch ------------------------------------------------------------
extern "C" void kernel_launch(void* const* d_in, const int* in_sizes, int n_in,
                              void* d_out, int out_size)
{
    const float* x    = (const float*)d_in[0];
    const int*   edge = (const int*)d_in[1];   // int32 (JAX x64 disabled)
    const float* Wl[3] = {(const float*)d_in[2], (const float*)d_in[5], (const float*)d_in[8]};
    const float* bl[3] = {(const float*)d_in[3], (const float*)d_in[6], (const float*)d_in[9]};
    const float* Wr[3] = {(const float*)d_in[4], (const float*)d_in[7], (const float*)d_in[10]};
    const float* Wf = (const float*)d_in[11];
    const float* bf = (const float*)d_in[12];
    float* out = (float*)d_out;

    cudaFuncSetAttribute(k_gemm, cudaFuncAttributeMaxDynamicSharedMemorySize, SM_TOTAL);

    void* p = nullptr;
    cudaGetSymbolAddress(&p, g_xp);   unsigned* xp = (unsigned*)p;
    cudaGetSymbolAddress(&p, g_hp);   unsigned* h0p = (unsigned*)p;
    unsigned* h1p = h0p + (size_t)N_NODES * F;
    cudaGetSymbolAddress(&p, g_meanp); unsigned* mp = (unsigned*)p;
    cudaGetSymbolAddress(&p, g_xq);   short* xq = (short*)p;
    cudaGetSymbolAddress(&p, g_hq);   short* h0q = (short*)p;
    short* h1q = h0q + (size_t)N_NODES * F;
    cudaGetSymbolAddress(&p, g_sx);   float* sx = (float*)p;
    cudaGetSymbolAddress(&p, g_sh);   float* s0 = (float*)p;
    float* s1 = s0 + N_NODES;
    cudaGetSymbolAddress(&p, g_whi);  __nv_bfloat16* whi = (__nv_bfloat16*)p;
    cudaGetSymbolAddress(&p, g_wlo);  __nv_bfloat16* wlo = (__nv_bfloat16*)p;

    // prep + CSR
    k_prep<<<(N_NODES * F / 4 + 255) / 256, 256>>>(x, Wl[0], Wr[0], Wl[1], Wr[1], Wl[2], Wr[2]);
    k_hist<<<(N_EDGES + 255) / 256, 256>>>(edge);
    k_scan1<<<NSCAN, SCAN_BLK>>>();
    k_scan2<<<1, 64>>>();
    k_scan3<<<(N_NODES + 255) / 256, 256>>>();
    k_scatter<<<(N_EDGES + 255) / 256, 256>>>(edge);

    const int AGG_BLOCKS = (N_NODES * 32 + 255) / 256;
    const int GEMM_BLOCKS = (N_NODES + 127) / 128;   // 391

    // layer 0
    k_agg<<<AGG_BLOCKS, 256>>>(xq, sx);
    k_gemm<<<GEMM_BLOCKS, 256, SM_TOTAL>>>(mp, xp, whi, wlo, bl[0], h0p, h0q, s0);
    // layer 1
    k_agg<<<AGG_BLOCKS, 256>>>(h0q, s0);
    k_gemm<<<GEMM_BLOCKS, 256, SM_TOTAL>>>(mp, h0p, whi + 128 * 256, wlo + 128 * 256, bl[1], h1p, h1q, s1);
    // layer 2
    k_agg<<<AGG_BLOCKS, 256>>>(h1q, s1);
    k_gemm<<<GEMM_BLOCKS, 256, SM_TOTAL>>>(mp, h1p, whi + 2 * 128 * 256, wlo + 2 * 128 * 256, bl[2], h0p, h0q, s0);
    // final
    k_final<<<AGG_BLOCKS, 256>>>(h0p, Wf, bf, out);
}

// round 8
// speedup vs baseline: 1.2167x; 1.0855x over previous
#include <cuda_runtime.h>
#include <cuda_bf16.h>
#include <cstdint>

#define N_NODES 50000
#define N_EDGES 800000
#define F 128
#define SCAN_BLK 1024
#define NSCAN ((N_NODES + SCAN_BLK - 1) / SCAN_BLK)   // 49

// ---------------- scratch (static device memory) -----------------------------
__device__ unsigned g_xp[(size_t)N_NODES * F];          // packed split-bf16 x (hi lo)
__device__ unsigned g_hp[2][(size_t)N_NODES * F];       // packed hidden (ping-pong)
__device__ unsigned g_meanp[(size_t)N_NODES * F];       // packed mean
__device__ __nv_bfloat16 g_whi[3 * 128 * 256];          // combined [Wl|Wr] hi
__device__ __nv_bfloat16 g_wlo[3 * 128 * 256];          // combined [Wl|Wr] lo
__device__ int g_deg[N_NODES];
__device__ int g_scan[N_NODES];
__device__ int g_off[N_NODES];
__device__ int g_cursor[N_NODES];
__device__ int g_bsum[64];
__device__ int g_srcs[N_EDGES];

// ---------------- pack/unpack helpers ----------------------------------------
__device__ __forceinline__ float unpack_v(unsigned u) {
    return __uint_as_float(u << 16) + __uint_as_float(u & 0xFFFF0000u);
}
__device__ __forceinline__ unsigned pack_v(float v) {
    __nv_bfloat16 h = __float2bfloat16(v);
    unsigned hb = (unsigned)__bfloat16_as_ushort(h);
    float hf = __uint_as_float(hb << 16);
    __nv_bfloat16 l = __float2bfloat16(v - hf);
    unsigned lb = (unsigned)__bfloat16_as_ushort(l);
    return hb | (lb << 16);
}

// ---------------- warp-mma helpers --------------------------------------------
__device__ __forceinline__ unsigned smem_u32(const void* p) {
    unsigned a;
    asm("{ .reg .u64 t; cvta.to.shared.u64 t, %1; cvt.u32.u64 %0, t; }" : "=r"(a) : "l"(p));
    return a;
}
__device__ __forceinline__ void ldsm_x4(unsigned* r, unsigned addr) {
    asm volatile("ldmatrix.sync.aligned.m8n8.x4.shared.b16 {%0,%1,%2,%3}, [%4];"
                 : "=r"(r[0]), "=r"(r[1]), "=r"(r[2]), "=r"(r[3]) : "r"(addr));
}
__device__ __forceinline__ void mma16816(float* c, const unsigned* a, const unsigned* b) {
    asm volatile(
        "mma.sync.aligned.m16n8k16.row.col.f32.bf16.bf16.f32 "
        "{%0,%1,%2,%3}, {%4,%5,%6,%7}, {%8,%9}, {%0,%1,%2,%3};"
        : "+f"(c[0]), "+f"(c[1]), "+f"(c[2]), "+f"(c[3])
        : "r"(a[0]), "r"(a[1]), "r"(a[2]), "r"(a[3]), "r"(b[0]), "r"(b[1]));
}

// ---------------- prep: zero deg + pack weights + pack x ------------------------
__global__ void k_prep(const float* __restrict__ x,
                       const float* Wl0, const float* Wr0,
                       const float* Wl1, const float* Wr1,
                       const float* Wl2, const float* Wr2) {
    int gid = blockIdx.x * blockDim.x + threadIdx.x;
    if (gid < N_NODES) g_deg[gid] = 0;
    if (gid < 3 * 128 * 256) {
        int L = gid / (128 * 256);
        int r = gid % (128 * 256);
        int n = r / 256;
        int k = r % 256;
        const float* Wl = (L == 0) ? Wl0 : (L == 1) ? Wl1 : Wl2;
        const float* Wr = (L == 0) ? Wr0 : (L == 1) ? Wr1 : Wr2;
        float v = (k < 128) ? Wl[n * 128 + k] : Wr[n * 128 + (k - 128)];
        unsigned p = pack_v(v);
        __nv_bfloat16_raw hr; hr.x = (unsigned short)(p & 0xFFFF);
        __nv_bfloat16_raw lr; lr.x = (unsigned short)(p >> 16);
        g_whi[gid] = __nv_bfloat16(hr);
        g_wlo[gid] = __nv_bfloat16(lr);
    }
    if (gid < N_NODES * F / 4) {
        float4 v = ((const float4*)x)[gid];
        uint4 o;
        o.x = pack_v(v.x); o.y = pack_v(v.y); o.z = pack_v(v.z); o.w = pack_v(v.w);
        ((uint4*)g_xp)[gid] = o;
    }
}

// ---------------- CSR build: vectorized hist/scatter ----------------------------
__global__ void k_hist(const int* __restrict__ edge) {
    int e4 = (blockIdx.x * blockDim.x + threadIdx.x) * 4;
    if (e4 + 3 < N_EDGES) {
        uint4 d = *(const uint4*)(edge + N_EDGES + e4);
        if (d.x < N_NODES) atomicAdd(&g_deg[d.x], 1);
        if (d.y < N_NODES) atomicAdd(&g_deg[d.y], 1);
        if (d.z < N_NODES) atomicAdd(&g_deg[d.z], 1);
        if (d.w < N_NODES) atomicAdd(&g_deg[d.w], 1);
    } else {
        for (int e = e4; e < N_EDGES; e++) {
            unsigned dst = (unsigned)edge[N_EDGES + e];
            if (dst < N_NODES) atomicAdd(&g_deg[dst], 1);
        }
    }
}

__global__ void k_scan1() {
    __shared__ int s[SCAN_BLK];
    int tid = threadIdx.x;
    int i = blockIdx.x * SCAN_BLK + tid;
    int v = (i < N_NODES) ? g_deg[i] : 0;
    s[tid] = v;
    __syncthreads();
    for (int o = 1; o < SCAN_BLK; o <<= 1) {
        int t = (tid >= o) ? s[tid - o] : 0;
        __syncthreads();
        s[tid] += t;
        __syncthreads();
    }
    if (i < N_NODES) g_scan[i] = s[tid];
    if (tid == SCAN_BLK - 1) g_bsum[blockIdx.x] = s[tid];
}

// scan2 folded in: every block redundantly scans the 49 block sums in smem
__global__ void k_scan23() {
    __shared__ int bx[64];
    int tid = threadIdx.x;
    if (tid < 64) {
        int v = (tid < NSCAN) ? g_bsum[tid] : 0;
        bx[tid] = v;
    }
    __syncthreads();
    if (tid == 0) {           // serial exclusive scan of 49 ints (trivial)
        int run = 0;
        for (int b = 0; b < NSCAN; b++) {
            int v = bx[b];
            bx[b] = run;
            run += v;
        }
    }
    __syncthreads();
    int i = blockIdx.x * blockDim.x + tid;
    if (i < N_NODES) {
        int off = g_scan[i] - g_deg[i] + bx[i / SCAN_BLK];
        g_off[i] = off;
        g_cursor[i] = off;
    }
}

__global__ void k_scatter(const int* __restrict__ edge) {
    int e4 = (blockIdx.x * blockDim.x + threadIdx.x) * 4;
    if (e4 + 3 < N_EDGES) {
        uint4 s = *(const uint4*)(edge + e4);
        uint4 d = *(const uint4*)(edge + N_EDGES + e4);
        if (d.x < N_NODES && s.x < N_NODES) g_srcs[atomicAdd(&g_cursor[d.x], 1)] = (int)s.x;
        if (d.y < N_NODES && s.y < N_NODES) g_srcs[atomicAdd(&g_cursor[d.y], 1)] = (int)s.y;
        if (d.z < N_NODES && s.z < N_NODES) g_srcs[atomicAdd(&g_cursor[d.z], 1)] = (int)s.z;
        if (d.w < N_NODES && s.w < N_NODES) g_srcs[atomicAdd(&g_cursor[d.w], 1)] = (int)s.w;
    } else {
        for (int e = e4; e < N_EDGES; e++) {
            unsigned src = (unsigned)edge[e];
            unsigned dst = (unsigned)edge[N_EDGES + e];
            if (dst < N_NODES && src < N_NODES)
                g_srcs[atomicAdd(&g_cursor[dst], 1)] = (int)src;
        }
    }
}

// ---------------- aggregation: one warp per node (R4 exact) ---------------------
__global__ void k_agg(const unsigned* __restrict__ in) {
    int node = (blockIdx.x * blockDim.x + threadIdx.x) >> 5;
    if (node >= N_NODES) return;
    int lane = threadIdx.x & 31;
    int d = g_deg[node];
    int o = g_off[node];
    float a0 = 0.f, a1 = 0.f, a2 = 0.f, a3 = 0.f;
    for (int e = 0; e < d; e++) {
        int s = g_srcs[o + e];
        uint4 p = ((const uint4*)(in + (size_t)s * F))[lane];
        a0 += unpack_v(p.x); a1 += unpack_v(p.y);
        a2 += unpack_v(p.z); a3 += unpack_v(p.w);
    }
    float inv = (d > 0) ? 1.0f / (float)d : 0.0f;
    uint4 outp;
    outp.x = pack_v(a0 * inv); outp.y = pack_v(a1 * inv);
    outp.z = pack_v(a2 * inv); outp.w = pack_v(a3 * inv);
    ((uint4*)(g_meanp + (size_t)node * F))[lane] = outp;
}

// ---------------- HMMA GEMM (R4 exact) -------------------------------------------
#define SM_BIAS 0
#define SM_AHI  512
#define SM_ALO  (SM_AHI + 16384)
#define SM_WHI  (SM_ALO + 16384)
#define SM_WLO  (SM_WHI + 16384)
#define SM_TOTAL (SM_WLO + 16384)     // 66048 bytes

__device__ __forceinline__ unsigned swoff(int row, int k) {
    return (unsigned)(row * 128 + ((((k >> 3) ^ row) & 7) << 4) + (k & 7) * 2);
}

__global__ void __launch_bounds__(256, 1) k_gemm(
    const unsigned* __restrict__ Am,
    const unsigned* __restrict__ Ah,
    const __nv_bfloat16* __restrict__ Whi,
    const __nv_bfloat16* __restrict__ Wlo,
    const float* __restrict__ bl,
    unsigned* __restrict__ outp)
{
    extern __shared__ __align__(16) char smem[];
    unsigned sb = smem_u32(smem);
    int tid = threadIdx.x;
    int wid = tid >> 5;
    int lane = tid & 31;
    int wm = wid & 1;
    int wn = wid >> 1;
    int m0 = blockIdx.x * 128;

    if (tid < 128) *(float*)(smem + SM_BIAS + tid * 4) = bl[tid];

    float acc[4][4][4];
#pragma unroll
    for (int a = 0; a < 4; a++)
#pragma unroll
        for (int b = 0; b < 4; b++)
#pragma unroll
            for (int c = 0; c < 4; c++) acc[a][b][c] = 0.f;

    for (int chunk = 0; chunk < 4; chunk++) {
        const unsigned* ap = (chunk < 2) ? Am : Ah;
        int kcA = (chunk & 1) * 64;
        int kcW = chunk * 64;
        __syncthreads();
        for (int i = tid; i < 2048; i += 256) {
            int row = i >> 4;
            int k4 = (i & 15) * 4;
            uint4 p = make_uint4(0, 0, 0, 0);
            if (m0 + row < N_NODES)
                p = *(const uint4*)(ap + (size_t)(m0 + row) * F + kcA + k4);
            uint2 h, l;
            h.x = (p.x & 0xFFFFu) | (p.y << 16);
            h.y = (p.z & 0xFFFFu) | (p.w << 16);
            l.x = (p.x >> 16) | (p.y & 0xFFFF0000u);
            l.y = (p.z >> 16) | (p.w & 0xFFFF0000u);
            unsigned off = swoff(row, k4);
            *(uint2*)(smem + SM_AHI + off) = h;
            *(uint2*)(smem + SM_ALO + off) = l;
        }
        for (int i = tid; i < 1024; i += 256) {
            int n = i >> 3;
            int k8 = (i & 7) * 8;
            unsigned off = swoff(n, k8);
            *(uint4*)(smem + SM_WHI + off) = *(const uint4*)(Whi + n * 256 + kcW + k8);
            *(uint4*)(smem + SM_WLO + off) = *(const uint4*)(Wlo + n * 256 + kcW + k8);
        }
        __syncthreads();

#pragma unroll
        for (int ks = 0; ks < 4; ks++) {
            int kl = ks * 16;
            unsigned ahi[16], alo[16];
            int mrl = ((lane >> 3) & 1) * 8 + (lane & 7);
            int kkA = kl + (lane >> 4) * 8;
#pragma unroll
            for (int mf = 0; mf < 4; mf++) {
                int mrow = wm * 64 + mf * 16 + mrl;
                unsigned offA = (unsigned)(mrow * 128 + ((((kkA >> 3) ^ mrow) & 7) << 4));
                ldsm_x4(&ahi[mf * 4], sb + SM_AHI + offA);
                ldsm_x4(&alo[mf * 4], sb + SM_ALO + offA);
            }
            unsigned bhi[8], blo[8];
            int nrl = (lane >> 4) * 8 + (lane & 7);
            int kkB = kl + ((lane >> 3) & 1) * 8;
#pragma unroll
            for (int nf2 = 0; nf2 < 2; nf2++) {
                int nrow = wn * 32 + nf2 * 16 + nrl;
                unsigned offB = (unsigned)(nrow * 128 + ((((kkB >> 3) ^ nrow) & 7) << 4));
                ldsm_x4(&bhi[nf2 * 4], sb + SM_WHI + offB);
                ldsm_x4(&blo[nf2 * 4], sb + SM_WLO + offB);
            }
#pragma unroll
            for (int mf = 0; mf < 4; mf++)
#pragma unroll
                for (int nf = 0; nf < 4; nf++) {
                    const unsigned* bh = &bhi[(nf >> 1) * 4 + (nf & 1) * 2];
                    const unsigned* blp = &blo[(nf >> 1) * 4 + (nf & 1) * 2];
                    mma16816(acc[mf][nf], &ahi[mf * 4], bh);
                    mma16816(acc[mf][nf], &ahi[mf * 4], blp);
                    mma16816(acc[mf][nf], &alo[mf * 4], bh);
                }
        }
    }

    // epilogue: bias + relu + pack (R4 exact)
    const float* bias = (const float*)(smem + SM_BIAS);
#pragma unroll
    for (int mf = 0; mf < 4; mf++) {
        int ra = m0 + wm * 64 + mf * 16 + (lane >> 2);
        int rb = ra + 8;
#pragma unroll
        for (int nf = 0; nf < 4; nf++) {
            int col = wn * 32 + nf * 8 + (lane & 3) * 2;
            float b0 = bias[col], b1 = bias[col + 1];
            if (ra < N_NODES) {
                float v0 = fmaxf(acc[mf][nf][0] + b0, 0.f);
                float v1 = fmaxf(acc[mf][nf][1] + b1, 0.f);
                *(uint2*)(outp + (size_t)ra * F + col) = make_uint2(pack_v(v0), pack_v(v1));
            }
            if (rb < N_NODES) {
                float v2 = fmaxf(acc[mf][nf][2] + b0, 0.f);
                float v3 = fmaxf(acc[mf][nf][3] + b1, 0.f);
                *(uint2*)(outp + (size_t)rb * F + col) = make_uint2(pack_v(v2), pack_v(v3));
            }
        }
    }
}

// ---------------- final linear ---------------------------------------------------
__global__ void k_final(const unsigned* __restrict__ h,
                        const float* __restrict__ Wf,
                        const float* __restrict__ bf,
                        float* __restrict__ out)
{
    int node = (blockIdx.x * blockDim.x + threadIdx.x) >> 5;
    if (node >= N_NODES) return;
    int lane = threadIdx.x & 31;
    uint4 p = ((const uint4*)(h + (size_t)node * F))[lane];
    float4 wv = ((const float4*)Wf)[lane];
    float s = unpack_v(p.x) * wv.x + unpack_v(p.y) * wv.y +
              unpack_v(p.z) * wv.z + unpack_v(p.w) * wv.w;
#pragma unroll
    for (int o = 16; o > 0; o >>= 1) s += __shfl_down_sync(0xFFFFFFFFu, s, o);
    if (lane == 0) out[node] = s + bf[0];
}

// ---------------- launch ------------------------------------------------------------
extern "C" void kernel_launch(void* const* d_in, const int* in_sizes, int n_in,
                              void* d_out, int out_size)
{
    const float* x    = (const float*)d_in[0];
    const int*   edge = (const int*)d_in[1];   // int32 (JAX x64 disabled)
    const float* Wl[3] = {(const float*)d_in[2], (const float*)d_in[5], (const float*)d_in[8]};
    const float* bl[3] = {(const float*)d_in[3], (const float*)d_in[6], (const float*)d_in[9]};
    const float* Wr[3] = {(const float*)d_in[4], (const float*)d_in[7], (const float*)d_in[10]};
    const float* Wf = (const float*)d_in[11];
    const float* bf = (const float*)d_in[12];
    float* out = (float*)d_out;

    cudaFuncSetAttribute(k_gemm, cudaFuncAttributeMaxDynamicSharedMemorySize, SM_TOTAL);

    void* p = nullptr;
    cudaGetSymbolAddress(&p, g_xp);
    unsigned* xp = (unsigned*)p;
    cudaGetSymbolAddress(&p, g_hp);
    unsigned* h0 = (unsigned*)p;
    unsigned* h1 = h0 + (size_t)N_NODES * F;
    cudaGetSymbolAddress(&p, g_meanp);
    unsigned* mp = (unsigned*)p;
    cudaGetSymbolAddress(&p, g_whi);
    __nv_bfloat16* whi = (__nv_bfloat16*)p;
    cudaGetSymbolAddress(&p, g_wlo);
    __nv_bfloat16* wlo = (__nv_bfloat16*)p;

    // prep (zero deg + pack W + pack x), then CSR build
    k_prep<<<(N_NODES * F / 4 + 255) / 256, 256>>>(x, Wl[0], Wr[0], Wl[1], Wr[1], Wl[2], Wr[2]);
    k_hist<<<(N_EDGES / 4 + 255) / 256, 256>>>(edge);
    k_scan1<<<NSCAN, SCAN_BLK>>>();
    k_scan23<<<(N_NODES + 255) / 256, 256>>>();
    k_scatter<<<(N_EDGES / 4 + 255) / 256, 256>>>(edge);

    const int AGG_BLOCKS = (N_NODES * 32 + 255) / 256;
    const int GEMM_BLOCKS = (N_NODES + 127) / 128;   // 391

    // layer 0
    k_agg<<<AGG_BLOCKS, 256>>>(xp);
    k_gemm<<<GEMM_BLOCKS, 256, SM_TOTAL>>>(mp, xp, whi, wlo, bl[0], h0);
    // layer 1
    k_agg<<<AGG_BLOCKS, 256>>>(h0);
    k_gemm<<<GEMM_BLOCKS, 256, SM_TOTAL>>>(mp, h0, whi + 128 * 256, wlo + 128 * 256, bl[1], h1);
    // layer 2
    k_agg<<<AGG_BLOCKS, 256>>>(h1);
    k_gemm<<<GEMM_BLOCKS, 256, SM_TOTAL>>>(mp, h1, whi + 2 * 128 * 256, wlo + 2 * 128 * 256, bl[2], h0);
    // final
    k_final<<<AGG_BLOCKS, 256>>>(h0, Wf, bf, out);
}